// round 14
// baseline (speedup 1.0000x reference)
#include <cuda_runtime.h>
#include <cuda_bf16.h>
#include <math.h>
#include <stdint.h>

#define BB 16
#define PP 16384
#define MM 2048
#define D_Z 512
#define D_PHI 256
#define D_R 64
#define H1 96
#define H2 96

// scratch (no allocation allowed)
__device__ float g_A[BB * H1];
__device__ float g_Cp[PP * H1];
// precomputed bf16 hi/lo weights, [n][k2] layout (k2 = packed k-pair index)
__device__ uint32_t g_W1hi[96 * 416];
__device__ uint32_t g_W1lo[96 * 416];
__device__ uint32_t g_W2hi[96 * 48];
__device__ uint32_t g_W2lo[96 * 48];

// branch-free gelu: erf via Abramowitz-Stegun 7.1.26 (abs err <= 1.5e-7)
__device__ __forceinline__ float fast_gelu(float x) {
    float z  = x * 0.70710678118654752440f;
    float az = fabsf(z);
    float t  = __fdividef(1.0f, fmaf(0.3275911f, az, 1.0f));
    float p  = fmaf(1.061405429f, t, -1.453152027f);
    p = fmaf(p, t, 1.421413741f);
    p = fmaf(p, t, -0.284496736f);
    p = fmaf(p, t, 0.254829592f);
    p = p * t;
    float e = __expf(-z * z);
    float erfabs = fmaf(-p, e, 1.0f);
    float erfz = copysignf(erfabs, z);
    return 0.5f * x * (1.0f + erfz);
}

// ---- bf16 split helpers ----
__device__ __forceinline__ void bf16split(float x, unsigned short& h, unsigned short& l) {
    __nv_bfloat16 bh = __float2bfloat16_rn(x);
    float fh = __bfloat162float(bh);
    __nv_bfloat16 bl = __float2bfloat16_rn(x - fh);
    h = __bfloat16_as_ushort(bh);
    l = __bfloat16_as_ushort(bl);
}
__device__ __forceinline__ uint32_t packu(unsigned short lo16, unsigned short hi16) {
    return (uint32_t)lo16 | ((uint32_t)hi16 << 16);
}

__device__ __forceinline__ uint32_t smem_u32(const void* p) {
    return (uint32_t)__cvta_generic_to_shared(p);
}

// ldmatrix x4 (sm_75+ baseline)
__device__ __forceinline__ void ldm_x4(uint32_t& r0, uint32_t& r1,
                                       uint32_t& r2, uint32_t& r3, uint32_t addr) {
    asm volatile(
        "ldmatrix.sync.aligned.m8n8.x4.shared.b16 {%0,%1,%2,%3}, [%4];"
        : "=r"(r0), "=r"(r1), "=r"(r2), "=r"(r3) : "r"(addr));
}

// bf16 mma.sync (sm_80+ baseline)
__device__ __forceinline__ void mma_bf16(float* c,
                                         uint32_t a0, uint32_t a1, uint32_t a2, uint32_t a3,
                                         uint32_t b0, uint32_t b1) {
    asm volatile(
        "mma.sync.aligned.m16n8k16.row.col.f32.bf16.bf16.f32 "
        "{%0,%1,%2,%3}, {%4,%5,%6,%7}, {%8,%9}, {%0,%1,%2,%3};"
        : "+f"(c[0]), "+f"(c[1]), "+f"(c[2]), "+f"(c[3])
        : "r"(a0), "r"(a1), "r"(a2), "r"(a3), "r"(b0), "r"(b1));
}

// ---------------------------------------------------------------------------
// Kernel P: precompute bf16 hi/lo splits of W1[512:,:] and W2, [n][k2] layout.
// ---------------------------------------------------------------------------
__global__ void kP(const float* __restrict__ W1, const float* __restrict__ W2) {
    int idx = blockIdx.x * blockDim.x + threadIdx.x;
    if (idx < 96 * 416) {
        int n = idx / 416, k2 = idx - n * 416;
        float w0 = W1[(size_t)(D_Z + 2 * k2) * H1 + n];
        float w1 = W1[(size_t)(D_Z + 2 * k2 + 1) * H1 + n];
        unsigned short h0, l0, h1v, l1v;
        bf16split(w0, h0, l0);
        bf16split(w1, h1v, l1v);
        g_W1hi[idx] = packu(h0, h1v);
        g_W1lo[idx] = packu(l0, l1v);
    } else if (idx < 96 * 416 + 96 * 48) {
        int t = idx - 96 * 416;
        int n = t / 48, k2 = t - n * 48;
        float w0 = W2[(size_t)(2 * k2) * H2 + n];
        float w1 = W2[(size_t)(2 * k2 + 1) * H2 + n];
        unsigned short h0, l0, h1v, l1v;
        bf16split(w0, h0, l0);
        bf16split(w1, h1v, l1v);
        g_W2hi[t] = packu(h0, h1v);
        g_W2lo[t] = packu(l0, l1v);
    }
}

// ---------------------------------------------------------------------------
// Kernel A: A[b,j] = b1[j] + sum_k g_q[b,k] * W1[k,j]
// ---------------------------------------------------------------------------
__global__ void __launch_bounds__(768) kA(const float* __restrict__ g_q,
                                          const float* __restrict__ W1,
                                          const float* __restrict__ b1) {
    __shared__ float gq_sh[D_Z];
    __shared__ float psum[7 * 96];
    int b = blockIdx.x;
    int tid = threadIdx.x;
    for (int t = tid; t < D_Z; t += 768) gq_sh[t] = g_q[b * D_Z + t];
    __syncthreads();
    int ks = tid / 96, j = tid % 96;
    float s = 0.f;
    const float* w = W1 + (size_t)(ks * 64) * H1 + j;
    #pragma unroll 8
    for (int k = 0; k < 64; k++)
        s += gq_sh[ks * 64 + k] * w[(size_t)k * H1];
    if (ks > 0) psum[(ks - 1) * 96 + j] = s;
    __syncthreads();
    if (ks == 0) {
        #pragma unroll
        for (int i = 0; i < 7; i++) s += psum[i * 96 + j];
        g_A[b * H1 + j] = s + b1[j];
    }
}

// ---------------------------------------------------------------------------
// Kernel B (mma.sync bf16 hi/lo + ldmatrix): Cp[p,:] = feat(p,:) @ W1[512:,:]
// ---------------------------------------------------------------------------
#define KB_STR 36
#define KB_ROWS 64

__global__ void __launch_bounds__(256, 2) kB(const float* __restrict__ Phi,
                                             const void* __restrict__ pair_index,
                                             const float* __restrict__ rel) {
    __shared__ uint32_t Ahi[KB_ROWS * KB_STR];
    __shared__ uint32_t Alo[KB_ROWS * KB_STR];
    __shared__ uint32_t Whi[96 * KB_STR];
    __shared__ uint32_t Wlo[96 * KB_STR];
    __shared__ int pi_sh[KB_ROWS * 2];

    int tid  = threadIdx.x;
    int wid  = tid >> 5;
    int lane = tid & 31;
    int gid  = lane >> 2;
    int tig  = lane & 3;
    int p0   = blockIdx.x * KB_ROWS;

    {
        const int* p32 = (const int*)pair_index;
        int w = 0;
        if (tid < KB_ROWS * 2) w = p32[(size_t)p0 * 2 + tid];
        int any_odd = __syncthreads_or((tid & 1) ? w : 0);
        if (tid < KB_ROWS * 2) {
            int v;
            if (any_odd != 0) v = w;
            else {
                const long long* p64 = (const long long*)pair_index;
                v = (int)p64[(size_t)p0 * 2 + tid];
            }
            v = v < 0 ? 0 : (v >= MM ? MM - 1 : v);
            pi_sh[tid] = v;
        }
    }

    int mrow = (wid >> 1) * 16;
    int ncol = (wid & 1) * 48;

    // ldmatrix per-lane byte offsets (within tile, relative to smem base)
    uint32_t aoffB = ((uint32_t)((mrow + (lane & 15)) * KB_STR) +
                      ((lane & 16) ? 4u : 0u)) * 4u;
    uint32_t nrow_base = (uint32_t)(ncol + (lane & 7) + ((lane & 16) >> 1));
    uint32_t bcol = ((lane & 8) ? 4u : 0u);
    uint32_t boffB0 = ((nrow_base + 0)  * KB_STR + bcol) * 4u;
    uint32_t boffB2 = ((nrow_base + 16) * KB_STR + bcol) * 4u;
    uint32_t boffB4 = ((nrow_base + 32) * KB_STR + bcol) * 4u;

    uint32_t AhiB = smem_u32(Ahi), AloB = smem_u32(Alo);
    uint32_t WhiB = smem_u32(Whi), WloB = smem_u32(Wlo);

    float c[6][4];
    #pragma unroll
    for (int nt = 0; nt < 6; nt++)
        #pragma unroll
        for (int r = 0; r < 4; r++) c[nt][r] = 0.f;

    for (int ch = 0; ch < 13; ch++) {
        int mode  = ch >> 2;
        int cbase = (ch & 3) * 64;
        __syncthreads();

        #pragma unroll 2
        for (int idx = tid; idx < KB_ROWS * 32; idx += 256) {
            int pp  = idx >> 5;
            int kk2 = idx & 31;
            float f0, f1;
            if (mode == 3) {
                const float* rp = rel + (size_t)(p0 + pp) * D_R + kk2 * 2;
                f0 = rp[0]; f1 = rp[1];
            } else {
                int i0 = pi_sh[pp * 2];
                int j0 = pi_sh[pp * 2 + 1];
                const float* pi_ = Phi + (size_t)i0 * D_PHI + cbase + kk2 * 2;
                const float* pj_ = Phi + (size_t)j0 * D_PHI + cbase + kk2 * 2;
                float a0v = pi_[0], a1v = pi_[1];
                float c0v = pj_[0], c1v = pj_[1];
                if (mode == 0)      { f0 = a0v + c0v;        f1 = a1v + c1v; }
                else if (mode == 1) { f0 = fabsf(a0v - c0v); f1 = fabsf(a1v - c1v); }
                else                { f0 = a0v * c0v;        f1 = a1v * c1v; }
            }
            unsigned short h0, l0, h1v, l1v;
            bf16split(f0, h0, l0);
            bf16split(f1, h1v, l1v);
            Ahi[pp * KB_STR + kk2] = packu(h0, h1v);
            Alo[pp * KB_STR + kk2] = packu(l0, l1v);
        }

        #pragma unroll 4
        for (int idx = tid; idx < 96 * 32; idx += 256) {
            int n   = idx >> 5;
            int kk2 = idx & 31;
            Whi[n * KB_STR + kk2] = g_W1hi[n * 416 + ch * 32 + kk2];
            Wlo[n * KB_STR + kk2] = g_W1lo[n * 416 + ch * 32 + kk2];
        }
        __syncthreads();

        #pragma unroll
        for (int pass = 0; pass < 3; pass++) {
            uint32_t aB = ((pass == 1) ? AloB : AhiB) + aoffB;
            uint32_t bB = ((pass == 2) ? WloB : WhiB);
            uint32_t b0B = bB + boffB0, b2B = bB + boffB2, b4B = bB + boffB4;
            #pragma unroll
            for (int ks = 0; ks < 4; ks++) {
                uint32_t o = (uint32_t)ks * 32u;
                uint32_t a0, a1, a2, a3;
                uint32_t bf[12];
                ldm_x4(a0, a1, a2, a3, aB + o);
                ldm_x4(bf[0], bf[1], bf[2],  bf[3],  b0B + o);
                ldm_x4(bf[4], bf[5], bf[6],  bf[7],  b2B + o);
                ldm_x4(bf[8], bf[9], bf[10], bf[11], b4B + o);
                #pragma unroll
                for (int nt = 0; nt < 6; nt++)
                    mma_bf16(c[nt], a0, a1, a2, a3, bf[nt * 2], bf[nt * 2 + 1]);
            }
        }
    }

    #pragma unroll
    for (int rh = 0; rh < 2; rh++) {
        int row = mrow + rh * 8 + gid;
        float* o = g_Cp + (size_t)(p0 + row) * H1;
        #pragma unroll
        for (int nt = 0; nt < 6; nt++) {
            int col = ncol + nt * 8 + tig * 2;
            *(float2*)(o + col) = make_float2(c[nt][rh * 2], c[nt][rh * 2 + 1]);
        }
    }
}

// ---------------------------------------------------------------------------
// Kernel C (mma.sync bf16 hi/lo + ldmatrix, b-inner loop):
// out[b,p] = gelu(gelu(A[b]+Cp[p])@W2+b2)@W3+b3
// Block = 64 p-rows x 4 b (grid 256 x 4).
// ---------------------------------------------------------------------------
#define SA_STR 52
#define KC_ROWS 64
#define KC_BI 4
#define AHI_OFF 0
#define ALO_OFF 3328
#define BHI_OFF 6656
#define BLO_OFF 11648
#define AALL_OFF 16640
#define B2_OFF  17024
#define W3_OFF  17120
#define PS_OFF  17216
#define KC_SMEM_BYTES ((17216 + 128) * 4)

__global__ void __launch_bounds__(256, 3) kC(const float* __restrict__ b2,
                                             const float* __restrict__ W3,
                                             const float* __restrict__ b3,
                                             float* __restrict__ out) {
    extern __shared__ uint32_t smw[];
    uint32_t* Ahi = smw + AHI_OFF;      // 64 x 52
    uint32_t* Alo = smw + ALO_OFF;      // 64 x 52
    uint32_t* Bhi = smw + BHI_OFF;      // 96 x 52
    uint32_t* Blo = smw + BLO_OFF;      // 96 x 52
    float* Aall = (float*)(smw + AALL_OFF);  // KC_BI x 96
    float* b2f  = (float*)(smw + B2_OFF);
    float* W3f  = (float*)(smw + W3_OFF);
    float* ps   = (float*)(smw + PS_OFF);    // 2 x 64

    int tid  = threadIdx.x;
    int wid  = tid >> 5;
    int lane = tid & 31;
    int gid  = lane >> 2;
    int tig  = lane & 3;
    int p0   = blockIdx.x * KC_ROWS;
    int b0   = blockIdx.y * KC_BI;

    if (tid < 96) { b2f[tid] = b2[tid]; W3f[tid] = W3[tid]; }
    for (int idx = tid; idx < KC_BI * 96; idx += 256)
        Aall[idx] = g_A[b0 * H1 + idx];
    for (int idx = tid; idx < 96 * 48; idx += 256) {
        int n = idx / 48, k2 = idx - n * 48;
        Bhi[n * SA_STR + k2] = g_W2hi[idx];
        Blo[n * SA_STR + k2] = g_W2lo[idx];
    }

    // Cp rows into registers (reused for all KC_BI b-values)
    int row = tid >> 2, q4 = tid & 3;
    float cp[24];
    {
        const float4* cp4 = (const float4*)(g_Cp + (size_t)(p0 + row) * H1) + q4 * 6;
        #pragma unroll
        for (int q = 0; q < 6; q++) {
            float4 v = cp4[q];
            cp[q * 4 + 0] = v.x; cp[q * 4 + 1] = v.y;
            cp[q * 4 + 2] = v.z; cp[q * 4 + 3] = v.w;
        }
    }
    float b3v = b3[0];
    __syncthreads();

    int mrow = (wid >> 1) * 16;
    int ncol = (wid & 1) * 48;

    // ldmatrix per-lane byte offsets
    uint32_t aoffB = ((uint32_t)((mrow + (lane & 15)) * SA_STR) +
                      ((lane & 16) ? 4u : 0u)) * 4u;
    uint32_t nrow_base = (uint32_t)(ncol + (lane & 7) + ((lane & 16) >> 1));
    uint32_t bcol = ((lane & 8) ? 4u : 0u);
    uint32_t boffB0 = ((nrow_base + 0)  * SA_STR + bcol) * 4u;
    uint32_t boffB2 = ((nrow_base + 16) * SA_STR + bcol) * 4u;
    uint32_t boffB4 = ((nrow_base + 32) * SA_STR + bcol) * 4u;

    uint32_t AhiB = smem_u32(Ahi), AloB = smem_u32(Alo);
    uint32_t BhiB = smem_u32(Bhi), BloB = smem_u32(Blo);

    for (int bi = 0; bi < KC_BI; bi++) {
        // ---- build h1 = fast_gelu(A + cp), split hi/lo into smem ----
        {
            const float* Af = Aall + bi * 96 + q4 * 24;
            uint32_t* ah = Ahi + row * SA_STR + q4 * 12;
            uint32_t* al = Alo + row * SA_STR + q4 * 12;
            #pragma unroll
            for (int q = 0; q < 6; q++) {
                int k = q * 4;
                float g0 = fast_gelu(Af[k + 0] + cp[k + 0]);
                float g1 = fast_gelu(Af[k + 1] + cp[k + 1]);
                float g2 = fast_gelu(Af[k + 2] + cp[k + 2]);
                float g3 = fast_gelu(Af[k + 3] + cp[k + 3]);
                unsigned short h0, l0, h1v, l1v, h2, l2, h3, l3;
                bf16split(g0, h0, l0); bf16split(g1, h1v, l1v);
                bf16split(g2, h2, l2); bf16split(g3, h3, l3);
                ah[q * 2 + 0] = packu(h0, h1v);
                ah[q * 2 + 1] = packu(h2, h3);
                al[q * 2 + 0] = packu(l0, l1v);
                al[q * 2 + 1] = packu(l2, l3);
            }
        }
        __syncthreads();

        // ---- MMA: 3 passes x 6 k16-steps, warp tile 16x48 ----
        float c[6][4];
        #pragma unroll
        for (int nt = 0; nt < 6; nt++)
            #pragma unroll
            for (int r = 0; r < 4; r++) c[nt][r] = 0.f;

        #pragma unroll
        for (int pass = 0; pass < 3; pass++) {
            uint32_t aB = ((pass == 1) ? AloB : AhiB) + aoffB;
            uint32_t bB = ((pass == 2) ? BloB : BhiB);
            uint32_t b0B = bB + boffB0, b2B = bB + boffB2, b4B = bB + boffB4;
            #pragma unroll
            for (int ks = 0; ks < 6; ks++) {
                uint32_t o = (uint32_t)ks * 32u;
                uint32_t a0, a1, a2, a3;
                uint32_t bf[12];
                ldm_x4(a0, a1, a2, a3, aB + o);
                ldm_x4(bf[0], bf[1], bf[2],  bf[3],  b0B + o);
                ldm_x4(bf[4], bf[5], bf[6],  bf[7],  b2B + o);
                ldm_x4(bf[8], bf[9], bf[10], bf[11], b4B + o);
                #pragma unroll
                for (int nt = 0; nt < 6; nt++)
                    mma_bf16(c[nt], a0, a1, a2, a3, bf[nt * 2], bf[nt * 2 + 1]);
            }
        }

        // ---- epilogue: bias + gelu + W3-dot, shfl reduce, combine halves ----
        #pragma unroll
        for (int rh = 0; rh < 2; rh++) {
            float part = 0.f;
            #pragma unroll
            for (int nt = 0; nt < 6; nt++) {
                int col = ncol + nt * 8 + tig * 2;
                float v0 = c[nt][rh * 2 + 0] + b2f[col];
                float v1 = c[nt][rh * 2 + 1] + b2f[col + 1];
                part += fast_gelu(v0) * W3f[col];
                part += fast_gelu(v1) * W3f[col + 1];
            }
            part += __shfl_xor_sync(0xFFFFFFFF, part, 1);
            part += __shfl_xor_sync(0xFFFFFFFF, part, 2);
            if (tig == 0) {
                int rr = mrow + rh * 8 + gid;
                ps[(wid & 1) * KC_ROWS + rr] = part;
            }
        }
        __syncthreads();

        if (tid < KC_ROWS)
            out[(size_t)(b0 + bi) * PP + p0 + tid] =
                ps[tid] + ps[KC_ROWS + tid] + b3v;
        __syncthreads();
    }
}

// ---------------------------------------------------------------------------
extern "C" void kernel_launch(void* const* d_in, const int* in_sizes, int n_in,
                              void* d_out, int out_size) {
    const float* g_q = (const float*)d_in[0];
    const float* Phi = (const float*)d_in[1];
    const void*  pin = (const void*)d_in[2];
    const float* rel = (const float*)d_in[3];
    const float* W1  = (const float*)d_in[4];
    const float* b1  = (const float*)d_in[5];
    const float* W2  = (const float*)d_in[6];
    const float* b2  = (const float*)d_in[7];
    const float* W3  = (const float*)d_in[8];
    const float* b3  = (const float*)d_in[9];
    float* out = (float*)d_out;

    cudaFuncSetAttribute(kC, cudaFuncAttributeMaxDynamicSharedMemorySize,
                         KC_SMEM_BYTES);

    kP<<<(96 * 416 + 96 * 48 + 255) / 256, 256>>>(W1, W2);
    kB<<<PP / KB_ROWS, 256>>>(Phi, pin, rel);
    kA<<<BB, 768>>>(g_q, W1, b1);
    kC<<<dim3(PP / KC_ROWS, BB / KC_BI), 256, KC_SMEM_BYTES>>>(b2, W3, b3, out);
}

// round 15
// speedup vs baseline: 1.0652x; 1.0652x over previous
#include <cuda_runtime.h>
#include <cuda_bf16.h>
#include <math.h>
#include <stdint.h>

#define BB 16
#define PP 16384
#define MM 2048
#define D_Z 512
#define D_PHI 256
#define D_R 64
#define H1 96
#define H2 96

// scratch (no allocation allowed)
__device__ float g_A[BB * H1];
__device__ float g_Cp[PP * H1];
// precomputed bf16 hi/lo weights, [n][k2] layout (k2 = packed k-pair index)
__device__ uint32_t g_W1hi[96 * 416];
__device__ uint32_t g_W1lo[96 * 416];
__device__ uint32_t g_W2hi[96 * 48];
__device__ uint32_t g_W2lo[96 * 48];

// branch-free gelu: erf via Abramowitz-Stegun 7.1.26 (abs err <= 1.5e-7)
__device__ __forceinline__ float fast_gelu(float x) {
    float z  = x * 0.70710678118654752440f;
    float az = fabsf(z);
    float t  = __fdividef(1.0f, fmaf(0.3275911f, az, 1.0f));
    float p  = fmaf(1.061405429f, t, -1.453152027f);
    p = fmaf(p, t, 1.421413741f);
    p = fmaf(p, t, -0.284496736f);
    p = fmaf(p, t, 0.254829592f);
    p = p * t;
    float e = __expf(-z * z);
    float erfabs = fmaf(-p, e, 1.0f);
    float erfz = copysignf(erfabs, z);
    return 0.5f * x * (1.0f + erfz);
}

// ---- bf16 split helpers ----
__device__ __forceinline__ void bf16split(float x, unsigned short& h, unsigned short& l) {
    __nv_bfloat16 bh = __float2bfloat16_rn(x);
    float fh = __bfloat162float(bh);
    __nv_bfloat16 bl = __float2bfloat16_rn(x - fh);
    h = __bfloat16_as_ushort(bh);
    l = __bfloat16_as_ushort(bl);
}
__device__ __forceinline__ uint32_t packu(unsigned short lo16, unsigned short hi16) {
    return (uint32_t)lo16 | ((uint32_t)hi16 << 16);
}

// bf16 mma.sync (sm_80+ baseline, legal on compute_100)
__device__ __forceinline__ void mma_bf16(float* c,
                                         uint32_t a0, uint32_t a1, uint32_t a2, uint32_t a3,
                                         uint32_t b0, uint32_t b1) {
    asm volatile(
        "mma.sync.aligned.m16n8k16.row.col.f32.bf16.bf16.f32 "
        "{%0,%1,%2,%3}, {%4,%5,%6,%7}, {%8,%9}, {%0,%1,%2,%3};"
        : "+f"(c[0]), "+f"(c[1]), "+f"(c[2]), "+f"(c[3])
        : "r"(a0), "r"(a1), "r"(a2), "r"(a3), "r"(b0), "r"(b1));
}

// ---------------------------------------------------------------------------
// Kernel P: precompute bf16 hi/lo splits of W1[512:,:] and W2, [n][k2] layout.
// ---------------------------------------------------------------------------
__global__ void kP(const float* __restrict__ W1, const float* __restrict__ W2) {
    int idx = blockIdx.x * blockDim.x + threadIdx.x;
    if (idx < 96 * 416) {
        int n = idx / 416, k2 = idx - n * 416;
        float w0 = W1[(size_t)(D_Z + 2 * k2) * H1 + n];
        float w1 = W1[(size_t)(D_Z + 2 * k2 + 1) * H1 + n];
        unsigned short h0, l0, h1v, l1v;
        bf16split(w0, h0, l0);
        bf16split(w1, h1v, l1v);
        g_W1hi[idx] = packu(h0, h1v);
        g_W1lo[idx] = packu(l0, l1v);
    } else if (idx < 96 * 416 + 96 * 48) {
        int t = idx - 96 * 416;
        int n = t / 48, k2 = t - n * 48;
        float w0 = W2[(size_t)(2 * k2) * H2 + n];
        float w1 = W2[(size_t)(2 * k2 + 1) * H2 + n];
        unsigned short h0, l0, h1v, l1v;
        bf16split(w0, h0, l0);
        bf16split(w1, h1v, l1v);
        g_W2hi[t] = packu(h0, h1v);
        g_W2lo[t] = packu(l0, l1v);
    }
}

// ---------------------------------------------------------------------------
// Kernel A: A[b,j] = b1[j] + sum_k g_q[b,k] * W1[k,j]
// ---------------------------------------------------------------------------
__global__ void __launch_bounds__(768) kA(const float* __restrict__ g_q,
                                          const float* __restrict__ W1,
                                          const float* __restrict__ b1) {
    __shared__ float gq_sh[D_Z];
    __shared__ float psum[7 * 96];
    int b = blockIdx.x;
    int tid = threadIdx.x;
    for (int t = tid; t < D_Z; t += 768) gq_sh[t] = g_q[b * D_Z + t];
    __syncthreads();
    int ks = tid / 96, j = tid % 96;
    float s = 0.f;
    const float* w = W1 + (size_t)(ks * 64) * H1 + j;
    #pragma unroll 8
    for (int k = 0; k < 64; k++)
        s += gq_sh[ks * 64 + k] * w[(size_t)k * H1];
    if (ks > 0) psum[(ks - 1) * 96 + j] = s;
    __syncthreads();
    if (ks == 0) {
        #pragma unroll
        for (int i = 0; i < 7; i++) s += psum[i * 96 + j];
        g_A[b * H1 + j] = s + b1[j];
    }
}

// ---------------------------------------------------------------------------
// Kernel B (mma.sync bf16 hi/lo, scalar LDS fragments): Cp = feat @ W1[512:]
// 64 pairs/block, 256 threads, warp tile 16x48; now 3 blocks/SM.
// ---------------------------------------------------------------------------
#define KB_STR 36
#define KB_ROWS 64

__global__ void __launch_bounds__(256, 3) kB(const float* __restrict__ Phi,
                                             const void* __restrict__ pair_index,
                                             const float* __restrict__ rel) {
    __shared__ uint32_t Ahi[KB_ROWS * KB_STR];
    __shared__ uint32_t Alo[KB_ROWS * KB_STR];
    __shared__ uint32_t Whi[96 * KB_STR];
    __shared__ uint32_t Wlo[96 * KB_STR];
    __shared__ int pi_sh[KB_ROWS * 2];

    int tid  = threadIdx.x;
    int wid  = tid >> 5;
    int lane = tid & 31;
    int gid  = lane >> 2;
    int tig  = lane & 3;
    int p0   = blockIdx.x * KB_ROWS;

    {
        const int* p32 = (const int*)pair_index;
        int w = 0;
        if (tid < KB_ROWS * 2) w = p32[(size_t)p0 * 2 + tid];
        int any_odd = __syncthreads_or((tid & 1) ? w : 0);
        if (tid < KB_ROWS * 2) {
            int v;
            if (any_odd != 0) v = w;
            else {
                const long long* p64 = (const long long*)pair_index;
                v = (int)p64[(size_t)p0 * 2 + tid];
            }
            v = v < 0 ? 0 : (v >= MM ? MM - 1 : v);
            pi_sh[tid] = v;
        }
    }

    int mrow = (wid >> 1) * 16;
    int ncol = (wid & 1) * 48;

    float c[6][4];
    #pragma unroll
    for (int nt = 0; nt < 6; nt++)
        #pragma unroll
        for (int r = 0; r < 4; r++) c[nt][r] = 0.f;

    for (int ch = 0; ch < 13; ch++) {
        int mode  = ch >> 2;
        int cbase = (ch & 3) * 64;
        __syncthreads();

        #pragma unroll 2
        for (int idx = tid; idx < KB_ROWS * 32; idx += 256) {
            int pp  = idx >> 5;
            int kk2 = idx & 31;
            float f0, f1;
            if (mode == 3) {
                const float* rp = rel + (size_t)(p0 + pp) * D_R + kk2 * 2;
                f0 = rp[0]; f1 = rp[1];
            } else {
                int i0 = pi_sh[pp * 2];
                int j0 = pi_sh[pp * 2 + 1];
                const float* pi_ = Phi + (size_t)i0 * D_PHI + cbase + kk2 * 2;
                const float* pj_ = Phi + (size_t)j0 * D_PHI + cbase + kk2 * 2;
                float a0v = pi_[0], a1v = pi_[1];
                float c0v = pj_[0], c1v = pj_[1];
                if (mode == 0)      { f0 = a0v + c0v;        f1 = a1v + c1v; }
                else if (mode == 1) { f0 = fabsf(a0v - c0v); f1 = fabsf(a1v - c1v); }
                else                { f0 = a0v * c0v;        f1 = a1v * c1v; }
            }
            unsigned short h0, l0, h1v, l1v;
            bf16split(f0, h0, l0);
            bf16split(f1, h1v, l1v);
            Ahi[pp * KB_STR + kk2] = packu(h0, h1v);
            Alo[pp * KB_STR + kk2] = packu(l0, l1v);
        }

        #pragma unroll 4
        for (int idx = tid; idx < 96 * 32; idx += 256) {
            int n   = idx >> 5;
            int kk2 = idx & 31;
            Whi[n * KB_STR + kk2] = g_W1hi[n * 416 + ch * 32 + kk2];
            Wlo[n * KB_STR + kk2] = g_W1lo[n * 416 + ch * 32 + kk2];
        }
        __syncthreads();

        #pragma unroll
        for (int pass = 0; pass < 3; pass++) {
            const uint32_t* Ab = (pass == 1) ? Alo : Ahi;
            const uint32_t* Bb = (pass == 2) ? Wlo : Whi;
            #pragma unroll
            for (int ks = 0; ks < 4; ks++) {
                int kw = ks * 8;
                int r = mrow + gid;
                uint32_t a0 = Ab[(r)     * KB_STR + kw + tig];
                uint32_t a1 = Ab[(r + 8) * KB_STR + kw + tig];
                uint32_t a2 = Ab[(r)     * KB_STR + kw + 4 + tig];
                uint32_t a3 = Ab[(r + 8) * KB_STR + kw + 4 + tig];
                #pragma unroll
                for (int nt = 0; nt < 6; nt++) {
                    int n = ncol + nt * 8 + gid;
                    uint32_t b0 = Bb[n * KB_STR + kw + tig];
                    uint32_t b1v = Bb[n * KB_STR + kw + 4 + tig];
                    mma_bf16(c[nt], a0, a1, a2, a3, b0, b1v);
                }
            }
        }
    }

    #pragma unroll
    for (int rh = 0; rh < 2; rh++) {
        int row = mrow + rh * 8 + gid;
        float* o = g_Cp + (size_t)(p0 + row) * H1;
        #pragma unroll
        for (int nt = 0; nt < 6; nt++) {
            int col = ncol + nt * 8 + tig * 2;
            *(float2*)(o + col) = make_float2(c[nt][rh * 2], c[nt][rh * 2 + 1]);
        }
    }
}

// ---------------------------------------------------------------------------
// Kernel C (mma.sync bf16 hi/lo, b-inner loop, scalar LDS fragments):
// out[b,p] = gelu(gelu(A[b]+Cp[p])@W2+b2)@W3+b3
// Block = 64 p-rows x 4 b (grid 256 x 4). ps double-buffered -> 2 syncs/bi.
// ---------------------------------------------------------------------------
#define SA_STR 52
#define KC_ROWS 64
#define KC_BI 4
#define AHI_OFF 0
#define ALO_OFF 3328
#define BHI_OFF 6656
#define BLO_OFF 11648
#define AALL_OFF 16640
#define B2_OFF  17024
#define W3_OFF  17120
#define PS_OFF  17216
#define KC_SMEM_BYTES ((17216 + 256) * 4)

__global__ void __launch_bounds__(256, 3) kC(const float* __restrict__ b2,
                                             const float* __restrict__ W3,
                                             const float* __restrict__ b3,
                                             float* __restrict__ out) {
    extern __shared__ uint32_t smw[];
    uint32_t* Ahi = smw + AHI_OFF;      // 64 x 52
    uint32_t* Alo = smw + ALO_OFF;      // 64 x 52
    uint32_t* Bhi = smw + BHI_OFF;      // 96 x 52
    uint32_t* Blo = smw + BLO_OFF;      // 96 x 52
    float* Aall = (float*)(smw + AALL_OFF);  // KC_BI x 96
    float* b2f  = (float*)(smw + B2_OFF);
    float* W3f  = (float*)(smw + W3_OFF);
    float* ps   = (float*)(smw + PS_OFF);    // 2 buffers x 2 x 64

    int tid  = threadIdx.x;
    int wid  = tid >> 5;
    int lane = tid & 31;
    int gid  = lane >> 2;
    int tig  = lane & 3;
    int p0   = blockIdx.x * KC_ROWS;
    int b0   = blockIdx.y * KC_BI;

    if (tid < 96) { b2f[tid] = b2[tid]; W3f[tid] = W3[tid]; }
    for (int idx = tid; idx < KC_BI * 96; idx += 256)
        Aall[idx] = g_A[b0 * H1 + idx];
    for (int idx = tid; idx < 96 * 48; idx += 256) {
        int n = idx / 48, k2 = idx - n * 48;
        Bhi[n * SA_STR + k2] = g_W2hi[idx];
        Blo[n * SA_STR + k2] = g_W2lo[idx];
    }

    // Cp rows into registers (reused for all KC_BI b-values)
    int row = tid >> 2, q4 = tid & 3;
    float cp[24];
    {
        const float4* cp4 = (const float4*)(g_Cp + (size_t)(p0 + row) * H1) + q4 * 6;
        #pragma unroll
        for (int q = 0; q < 6; q++) {
            float4 v = cp4[q];
            cp[q * 4 + 0] = v.x; cp[q * 4 + 1] = v.y;
            cp[q * 4 + 2] = v.z; cp[q * 4 + 3] = v.w;
        }
    }
    float b3v = b3[0];
    __syncthreads();

    int mrow = (wid >> 1) * 16;
    int ncol = (wid & 1) * 48;

    for (int bi = 0; bi < KC_BI; bi++) {
        float* psb = ps + (bi & 1) * 128;

        // ---- build h1 = fast_gelu(A + cp), split hi/lo into smem ----
        {
            const float* Af = Aall + bi * 96 + q4 * 24;
            uint32_t* ah = Ahi + row * SA_STR + q4 * 12;
            uint32_t* al = Alo + row * SA_STR + q4 * 12;
            #pragma unroll
            for (int q = 0; q < 6; q++) {
                int k = q * 4;
                float g0 = fast_gelu(Af[k + 0] + cp[k + 0]);
                float g1 = fast_gelu(Af[k + 1] + cp[k + 1]);
                float g2 = fast_gelu(Af[k + 2] + cp[k + 2]);
                float g3 = fast_gelu(Af[k + 3] + cp[k + 3]);
                unsigned short h0, l0, h1v, l1v, h2, l2, h3, l3;
                bf16split(g0, h0, l0); bf16split(g1, h1v, l1v);
                bf16split(g2, h2, l2); bf16split(g3, h3, l3);
                ah[q * 2 + 0] = packu(h0, h1v);
                ah[q * 2 + 1] = packu(h2, h3);
                al[q * 2 + 0] = packu(l0, l1v);
                al[q * 2 + 1] = packu(l2, l3);
            }
        }
        __syncthreads();

        // ---- MMA: 3 passes x 6 k16-steps, warp tile 16x48 ----
        float c[6][4];
        #pragma unroll
        for (int nt = 0; nt < 6; nt++)
            #pragma unroll
            for (int r = 0; r < 4; r++) c[nt][r] = 0.f;

        #pragma unroll 1
        for (int pass = 0; pass < 3; pass++) {
            const uint32_t* Ab = (pass == 1) ? Alo : Ahi;
            const uint32_t* Bb = (pass == 2) ? Blo : Bhi;
            #pragma unroll
            for (int ks = 0; ks < 6; ks++) {
                int kw = ks * 8;
                int r = mrow + gid;
                uint32_t a0 = Ab[(r)     * SA_STR + kw + tig];
                uint32_t a1 = Ab[(r + 8) * SA_STR + kw + tig];
                uint32_t a2 = Ab[(r)     * SA_STR + kw + 4 + tig];
                uint32_t a3 = Ab[(r + 8) * SA_STR + kw + 4 + tig];
                #pragma unroll
                for (int nt = 0; nt < 6; nt++) {
                    int n = ncol + nt * 8 + gid;
                    uint32_t b0 = Bb[n * SA_STR + kw + tig];
                    uint32_t b1v = Bb[n * SA_STR + kw + 4 + tig];
                    mma_bf16(c[nt], a0, a1, a2, a3, b0, b1v);
                }
            }
        }

        // ---- epilogue: bias + gelu + W3-dot, shfl reduce, combine halves ----
        #pragma unroll
        for (int rh = 0; rh < 2; rh++) {
            float part = 0.f;
            #pragma unroll
            for (int nt = 0; nt < 6; nt++) {
                int col = ncol + nt * 8 + tig * 2;
                float v0 = c[nt][rh * 2 + 0] + b2f[col];
                float v1 = c[nt][rh * 2 + 1] + b2f[col + 1];
                part += fast_gelu(v0) * W3f[col];
                part += fast_gelu(v1) * W3f[col + 1];
            }
            part += __shfl_xor_sync(0xFFFFFFFF, part, 1);
            part += __shfl_xor_sync(0xFFFFFFFF, part, 2);
            if (tig == 0) {
                int rr = mrow + rh * 8 + gid;
                psb[(wid & 1) * KC_ROWS + rr] = part;
            }
        }
        __syncthreads();

        // out store reads psb; psb is not rewritten until bi+2's epilogue,
        // which is beyond bi+1's sync — no third barrier needed.
        if (tid < KC_ROWS)
            out[(size_t)(b0 + bi) * PP + p0 + tid] =
                psb[tid] + psb[KC_ROWS + tid] + b3v;
    }
}

// ---------------------------------------------------------------------------
extern "C" void kernel_launch(void* const* d_in, const int* in_sizes, int n_in,
                              void* d_out, int out_size) {
    const float* g_q = (const float*)d_in[0];
    const float* Phi = (const float*)d_in[1];
    const void*  pin = (const void*)d_in[2];
    const float* rel = (const float*)d_in[3];
    const float* W1  = (const float*)d_in[4];
    const float* b1  = (const float*)d_in[5];
    const float* W2  = (const float*)d_in[6];
    const float* b2  = (const float*)d_in[7];
    const float* W3  = (const float*)d_in[8];
    const float* b3  = (const float*)d_in[9];
    float* out = (float*)d_out;

    cudaFuncSetAttribute(kC, cudaFuncAttributeMaxDynamicSharedMemorySize,
                         KC_SMEM_BYTES);

    kP<<<(96 * 416 + 96 * 48 + 255) / 256, 256>>>(W1, W2);
    kB<<<PP / KB_ROWS, 256>>>(Phi, pin, rel);
    kA<<<BB, 768>>>(g_q, W1, b1);
    kC<<<dim3(PP / KC_ROWS, BB / KC_BI), 256, KC_SMEM_BYTES>>>(b2, W3, b3, out);
}

// round 16
// speedup vs baseline: 1.1494x; 1.0790x over previous
#include <cuda_runtime.h>
#include <cuda_bf16.h>
#include <math.h>
#include <stdint.h>

#define BB 16
#define PP 16384
#define MM 2048
#define D_Z 512
#define D_PHI 256
#define D_R 64
#define H1 96
#define H2 96

// scratch (no allocation allowed)
__device__ float g_A[BB * H1];
__device__ float g_Cp[PP * H1];
// precomputed bf16 hi/lo weights, [n][k2] layout (k2 = packed k-pair index)
__device__ uint32_t g_W1hi[96 * 416];
__device__ uint32_t g_W1lo[96 * 416];
__device__ uint32_t g_W2hi[96 * 48];
__device__ uint32_t g_W2lo[96 * 48];

// branch-free gelu: erf via Abramowitz-Stegun 7.1.26 (abs err <= 1.5e-7)
__device__ __forceinline__ float fast_gelu(float x) {
    float z  = x * 0.70710678118654752440f;
    float az = fabsf(z);
    float t  = __fdividef(1.0f, fmaf(0.3275911f, az, 1.0f));
    float p  = fmaf(1.061405429f, t, -1.453152027f);
    p = fmaf(p, t, 1.421413741f);
    p = fmaf(p, t, -0.284496736f);
    p = fmaf(p, t, 0.254829592f);
    p = p * t;
    float e = __expf(-z * z);
    float erfabs = fmaf(-p, e, 1.0f);
    float erfz = copysignf(erfabs, z);
    return 0.5f * x * (1.0f + erfz);
}

// ---- bf16 split helpers ----
__device__ __forceinline__ void bf16split(float x, unsigned short& h, unsigned short& l) {
    __nv_bfloat16 bh = __float2bfloat16_rn(x);
    float fh = __bfloat162float(bh);
    __nv_bfloat16 bl = __float2bfloat16_rn(x - fh);
    h = __bfloat16_as_ushort(bh);
    l = __bfloat16_as_ushort(bl);
}
__device__ __forceinline__ uint32_t packu(unsigned short lo16, unsigned short hi16) {
    return (uint32_t)lo16 | ((uint32_t)hi16 << 16);
}

// bf16 mma.sync (sm_80+ baseline, legal on compute_100)
__device__ __forceinline__ void mma_bf16(float* c,
                                         uint32_t a0, uint32_t a1, uint32_t a2, uint32_t a3,
                                         uint32_t b0, uint32_t b1) {
    asm volatile(
        "mma.sync.aligned.m16n8k16.row.col.f32.bf16.bf16.f32 "
        "{%0,%1,%2,%3}, {%4,%5,%6,%7}, {%8,%9}, {%0,%1,%2,%3};"
        : "+f"(c[0]), "+f"(c[1]), "+f"(c[2]), "+f"(c[3])
        : "r"(a0), "r"(a1), "r"(a2), "r"(a3), "r"(b0), "r"(b1));
}

// ---------------------------------------------------------------------------
// Kernel P: precompute bf16 hi/lo splits of W1[512:,:] and W2, [n][k2] layout.
// ---------------------------------------------------------------------------
__global__ void kP(const float* __restrict__ W1, const float* __restrict__ W2) {
    int idx = blockIdx.x * blockDim.x + threadIdx.x;
    if (idx < 96 * 416) {
        int n = idx / 416, k2 = idx - n * 416;
        float w0 = W1[(size_t)(D_Z + 2 * k2) * H1 + n];
        float w1 = W1[(size_t)(D_Z + 2 * k2 + 1) * H1 + n];
        unsigned short h0, l0, h1v, l1v;
        bf16split(w0, h0, l0);
        bf16split(w1, h1v, l1v);
        g_W1hi[idx] = packu(h0, h1v);
        g_W1lo[idx] = packu(l0, l1v);
    } else if (idx < 96 * 416 + 96 * 48) {
        int t = idx - 96 * 416;
        int n = t / 48, k2 = t - n * 48;
        float w0 = W2[(size_t)(2 * k2) * H2 + n];
        float w1 = W2[(size_t)(2 * k2 + 1) * H2 + n];
        unsigned short h0, l0, h1v, l1v;
        bf16split(w0, h0, l0);
        bf16split(w1, h1v, l1v);
        g_W2hi[t] = packu(h0, h1v);
        g_W2lo[t] = packu(l0, l1v);
    }
}

// ---------------------------------------------------------------------------
// Kernel A: A[b,j] = b1[j] + sum_k g_q[b,k] * W1[k,j]
// ---------------------------------------------------------------------------
__global__ void __launch_bounds__(768) kA(const float* __restrict__ g_q,
                                          const float* __restrict__ W1,
                                          const float* __restrict__ b1) {
    __shared__ float gq_sh[D_Z];
    __shared__ float psum[7 * 96];
    int b = blockIdx.x;
    int tid = threadIdx.x;
    for (int t = tid; t < D_Z; t += 768) gq_sh[t] = g_q[b * D_Z + t];
    __syncthreads();
    int ks = tid / 96, j = tid % 96;
    float s = 0.f;
    const float* w = W1 + (size_t)(ks * 64) * H1 + j;
    #pragma unroll 8
    for (int k = 0; k < 64; k++)
        s += gq_sh[ks * 64 + k] * w[(size_t)k * H1];
    if (ks > 0) psum[(ks - 1) * 96 + j] = s;
    __syncthreads();
    if (ks == 0) {
        #pragma unroll
        for (int i = 0; i < 7; i++) s += psum[i * 96 + j];
        g_A[b * H1 + j] = s + b1[j];
    }
}

// ---------------------------------------------------------------------------
// Kernel B (mma.sync bf16 hi/lo, fused 3-in-1 pass loop): Cp = feat @ W1[512:]
// 64 pairs/block, 256 threads, warp tile 16x48, 3 blocks/SM.
// ---------------------------------------------------------------------------
#define KB_STR 36
#define KB_ROWS 64

__global__ void __launch_bounds__(256, 3) kB(const float* __restrict__ Phi,
                                             const void* __restrict__ pair_index,
                                             const float* __restrict__ rel) {
    __shared__ uint32_t Ahi[KB_ROWS * KB_STR];
    __shared__ uint32_t Alo[KB_ROWS * KB_STR];
    __shared__ uint32_t Whi[96 * KB_STR];
    __shared__ uint32_t Wlo[96 * KB_STR];
    __shared__ int pi_sh[KB_ROWS * 2];

    int tid  = threadIdx.x;
    int wid  = tid >> 5;
    int lane = tid & 31;
    int gid  = lane >> 2;
    int tig  = lane & 3;
    int p0   = blockIdx.x * KB_ROWS;

    {
        const int* p32 = (const int*)pair_index;
        int w = 0;
        if (tid < KB_ROWS * 2) w = p32[(size_t)p0 * 2 + tid];
        int any_odd = __syncthreads_or((tid & 1) ? w : 0);
        if (tid < KB_ROWS * 2) {
            int v;
            if (any_odd != 0) v = w;
            else {
                const long long* p64 = (const long long*)pair_index;
                v = (int)p64[(size_t)p0 * 2 + tid];
            }
            v = v < 0 ? 0 : (v >= MM ? MM - 1 : v);
            pi_sh[tid] = v;
        }
    }

    int mrow = (wid >> 1) * 16;
    int ncol = (wid & 1) * 48;

    float c[6][4];
    #pragma unroll
    for (int nt = 0; nt < 6; nt++)
        #pragma unroll
        for (int r = 0; r < 4; r++) c[nt][r] = 0.f;

    for (int ch = 0; ch < 13; ch++) {
        int mode  = ch >> 2;
        int cbase = (ch & 3) * 64;
        __syncthreads();

        #pragma unroll 2
        for (int idx = tid; idx < KB_ROWS * 32; idx += 256) {
            int pp  = idx >> 5;
            int kk2 = idx & 31;
            float f0, f1;
            if (mode == 3) {
                const float* rp = rel + (size_t)(p0 + pp) * D_R + kk2 * 2;
                f0 = rp[0]; f1 = rp[1];
            } else {
                int i0 = pi_sh[pp * 2];
                int j0 = pi_sh[pp * 2 + 1];
                const float* pi_ = Phi + (size_t)i0 * D_PHI + cbase + kk2 * 2;
                const float* pj_ = Phi + (size_t)j0 * D_PHI + cbase + kk2 * 2;
                float a0v = pi_[0], a1v = pi_[1];
                float c0v = pj_[0], c1v = pj_[1];
                if (mode == 0)      { f0 = a0v + c0v;        f1 = a1v + c1v; }
                else if (mode == 1) { f0 = fabsf(a0v - c0v); f1 = fabsf(a1v - c1v); }
                else                { f0 = a0v * c0v;        f1 = a1v * c1v; }
            }
            unsigned short h0, l0, h1v, l1v;
            bf16split(f0, h0, l0);
            bf16split(f1, h1v, l1v);
            Ahi[pp * KB_STR + kk2] = packu(h0, h1v);
            Alo[pp * KB_STR + kk2] = packu(l0, l1v);
        }

        #pragma unroll 4
        for (int idx = tid; idx < 96 * 32; idx += 256) {
            int n   = idx >> 5;
            int kk2 = idx & 31;
            Whi[n * KB_STR + kk2] = g_W1hi[n * 416 + ch * 32 + kk2];
            Wlo[n * KB_STR + kk2] = g_W1lo[n * 416 + ch * 32 + kk2];
        }
        __syncthreads();

        // fused hi/lo: per k-step load Ahi+Alo once, per n-tile Bhi+Blo once,
        // issue 3 MMAs (AhiBhi, AloBhi, AhiBlo)
        #pragma unroll
        for (int ks = 0; ks < 4; ks++) {
            int kw = ks * 8;
            int r = mrow + gid;
            uint32_t ah0 = Ahi[(r)     * KB_STR + kw + tig];
            uint32_t ah1 = Ahi[(r + 8) * KB_STR + kw + tig];
            uint32_t ah2 = Ahi[(r)     * KB_STR + kw + 4 + tig];
            uint32_t ah3 = Ahi[(r + 8) * KB_STR + kw + 4 + tig];
            uint32_t al0 = Alo[(r)     * KB_STR + kw + tig];
            uint32_t al1 = Alo[(r + 8) * KB_STR + kw + tig];
            uint32_t al2 = Alo[(r)     * KB_STR + kw + 4 + tig];
            uint32_t al3 = Alo[(r + 8) * KB_STR + kw + 4 + tig];
            #pragma unroll
            for (int nt = 0; nt < 6; nt++) {
                int n = ncol + nt * 8 + gid;
                uint32_t bh0 = Whi[n * KB_STR + kw + tig];
                uint32_t bh1 = Whi[n * KB_STR + kw + 4 + tig];
                uint32_t bl0 = Wlo[n * KB_STR + kw + tig];
                uint32_t bl1 = Wlo[n * KB_STR + kw + 4 + tig];
                mma_bf16(c[nt], ah0, ah1, ah2, ah3, bh0, bh1);
                mma_bf16(c[nt], al0, al1, al2, al3, bh0, bh1);
                mma_bf16(c[nt], ah0, ah1, ah2, ah3, bl0, bl1);
            }
        }
    }

    #pragma unroll
    for (int rh = 0; rh < 2; rh++) {
        int row = mrow + rh * 8 + gid;
        float* o = g_Cp + (size_t)(p0 + row) * H1;
        #pragma unroll
        for (int nt = 0; nt < 6; nt++) {
            int col = ncol + nt * 8 + tig * 2;
            *(float2*)(o + col) = make_float2(c[nt][rh * 2], c[nt][rh * 2 + 1]);
        }
    }
}

// ---------------------------------------------------------------------------
// Kernel C (mma.sync bf16 hi/lo, fused 3-in-1 pass loop, b-inner loop):
// out[b,p] = gelu(gelu(A[b]+Cp[p])@W2+b2)@W3+b3
// Block = 64 p-rows x 4 b (grid 256 x 4), 3 blocks/SM.
// ---------------------------------------------------------------------------
#define SA_STR 52
#define KC_ROWS 64
#define KC_BI 4
#define AHI_OFF 0
#define ALO_OFF 3328
#define BHI_OFF 6656
#define BLO_OFF 11648
#define AALL_OFF 16640
#define B2_OFF  17024
#define W3_OFF  17120
#define PS_OFF  17216
#define KC_SMEM_BYTES ((17216 + 128) * 4)

__global__ void __launch_bounds__(256, 3) kC(const float* __restrict__ b2,
                                             const float* __restrict__ W3,
                                             const float* __restrict__ b3,
                                             float* __restrict__ out) {
    extern __shared__ uint32_t smw[];
    uint32_t* Ahi = smw + AHI_OFF;      // 64 x 52
    uint32_t* Alo = smw + ALO_OFF;      // 64 x 52
    uint32_t* Bhi = smw + BHI_OFF;      // 96 x 52
    uint32_t* Blo = smw + BLO_OFF;      // 96 x 52
    float* Aall = (float*)(smw + AALL_OFF);  // KC_BI x 96
    float* b2f  = (float*)(smw + B2_OFF);
    float* W3f  = (float*)(smw + W3_OFF);
    float* ps   = (float*)(smw + PS_OFF);    // 2 x 64

    int tid  = threadIdx.x;
    int wid  = tid >> 5;
    int lane = tid & 31;
    int gid  = lane >> 2;
    int tig  = lane & 3;
    int p0   = blockIdx.x * KC_ROWS;
    int b0   = blockIdx.y * KC_BI;

    if (tid < 96) { b2f[tid] = b2[tid]; W3f[tid] = W3[tid]; }
    for (int idx = tid; idx < KC_BI * 96; idx += 256)
        Aall[idx] = g_A[b0 * H1 + idx];
    for (int idx = tid; idx < 96 * 48; idx += 256) {
        int n = idx / 48, k2 = idx - n * 48;
        Bhi[n * SA_STR + k2] = g_W2hi[idx];
        Blo[n * SA_STR + k2] = g_W2lo[idx];
    }

    // Cp rows into registers (reused for all KC_BI b-values)
    int row = tid >> 2, q4 = tid & 3;
    float cp[24];
    {
        const float4* cp4 = (const float4*)(g_Cp + (size_t)(p0 + row) * H1) + q4 * 6;
        #pragma unroll
        for (int q = 0; q < 6; q++) {
            float4 v = cp4[q];
            cp[q * 4 + 0] = v.x; cp[q * 4 + 1] = v.y;
            cp[q * 4 + 2] = v.z; cp[q * 4 + 3] = v.w;
        }
    }
    float b3v = b3[0];
    __syncthreads();

    int mrow = (wid >> 1) * 16;
    int ncol = (wid & 1) * 48;

    for (int bi = 0; bi < KC_BI; bi++) {
        // ---- build h1 = fast_gelu(A + cp), split hi/lo into smem ----
        {
            const float* Af = Aall + bi * 96 + q4 * 24;
            uint32_t* ah = Ahi + row * SA_STR + q4 * 12;
            uint32_t* al = Alo + row * SA_STR + q4 * 12;
            #pragma unroll
            for (int q = 0; q < 6; q++) {
                int k = q * 4;
                float g0 = fast_gelu(Af[k + 0] + cp[k + 0]);
                float g1 = fast_gelu(Af[k + 1] + cp[k + 1]);
                float g2 = fast_gelu(Af[k + 2] + cp[k + 2]);
                float g3 = fast_gelu(Af[k + 3] + cp[k + 3]);
                unsigned short h0, l0, h1v, l1v, h2, l2, h3, l3;
                bf16split(g0, h0, l0); bf16split(g1, h1v, l1v);
                bf16split(g2, h2, l2); bf16split(g3, h3, l3);
                ah[q * 2 + 0] = packu(h0, h1v);
                ah[q * 2 + 1] = packu(h2, h3);
                al[q * 2 + 0] = packu(l0, l1v);
                al[q * 2 + 1] = packu(l2, l3);
            }
        }
        __syncthreads();

        // ---- MMA: fused hi/lo, 6 k16-steps, warp tile 16x48 ----
        float c[6][4];
        #pragma unroll
        for (int nt = 0; nt < 6; nt++)
            #pragma unroll
            for (int r = 0; r < 4; r++) c[nt][r] = 0.f;

        #pragma unroll
        for (int ks = 0; ks < 6; ks++) {
            int kw = ks * 8;
            int r = mrow + gid;
            uint32_t ah0 = Ahi[(r)     * SA_STR + kw + tig];
            uint32_t ah1 = Ahi[(r + 8) * SA_STR + kw + tig];
            uint32_t ah2 = Ahi[(r)     * SA_STR + kw + 4 + tig];
            uint32_t ah3 = Ahi[(r + 8) * SA_STR + kw + 4 + tig];
            uint32_t al0 = Alo[(r)     * SA_STR + kw + tig];
            uint32_t al1 = Alo[(r + 8) * SA_STR + kw + tig];
            uint32_t al2 = Alo[(r)     * SA_STR + kw + 4 + tig];
            uint32_t al3 = Alo[(r + 8) * SA_STR + kw + 4 + tig];
            #pragma unroll
            for (int nt = 0; nt < 6; nt++) {
                int n = ncol + nt * 8 + gid;
                uint32_t bh0 = Bhi[n * SA_STR + kw + tig];
                uint32_t bh1 = Bhi[n * SA_STR + kw + 4 + tig];
                uint32_t bl0 = Blo[n * SA_STR + kw + tig];
                uint32_t bl1 = Blo[n * SA_STR + kw + 4 + tig];
                mma_bf16(c[nt], ah0, ah1, ah2, ah3, bh0, bh1);
                mma_bf16(c[nt], al0, al1, al2, al3, bh0, bh1);
                mma_bf16(c[nt], ah0, ah1, ah2, ah3, bl0, bl1);
            }
        }

        // ---- epilogue: bias + gelu + W3-dot, shfl reduce, combine halves ----
        #pragma unroll
        for (int rh = 0; rh < 2; rh++) {
            float part = 0.f;
            #pragma unroll
            for (int nt = 0; nt < 6; nt++) {
                int col = ncol + nt * 8 + tig * 2;
                float v0 = c[nt][rh * 2 + 0] + b2f[col];
                float v1 = c[nt][rh * 2 + 1] + b2f[col + 1];
                part += fast_gelu(v0) * W3f[col];
                part += fast_gelu(v1) * W3f[col + 1];
            }
            part += __shfl_xor_sync(0xFFFFFFFF, part, 1);
            part += __shfl_xor_sync(0xFFFFFFFF, part, 2);
            if (tig == 0) {
                int rr = mrow + rh * 8 + gid;
                ps[(wid & 1) * KC_ROWS + rr] = part;
            }
        }
        __syncthreads();

        if (tid < KC_ROWS)
            out[(size_t)(b0 + bi) * PP + p0 + tid] =
                ps[tid] + ps[KC_ROWS + tid] + b3v;
        __syncthreads();
    }
}

// ---------------------------------------------------------------------------
extern "C" void kernel_launch(void* const* d_in, const int* in_sizes, int n_in,
                              void* d_out, int out_size) {
    const float* g_q = (const float*)d_in[0];
    const float* Phi = (const float*)d_in[1];
    const void*  pin = (const void*)d_in[2];
    const float* rel = (const float*)d_in[3];
    const float* W1  = (const float*)d_in[4];
    const float* b1  = (const float*)d_in[5];
    const float* W2  = (const float*)d_in[6];
    const float* b2  = (const float*)d_in[7];
    const float* W3  = (const float*)d_in[8];
    const float* b3  = (const float*)d_in[9];
    float* out = (float*)d_out;

    cudaFuncSetAttribute(kC, cudaFuncAttributeMaxDynamicSharedMemorySize,
                         KC_SMEM_BYTES);

    kP<<<(96 * 416 + 96 * 48 + 255) / 256, 256>>>(W1, W2);
    kB<<<PP / KB_ROWS, 256>>>(Phi, pin, rel);
    kA<<<BB, 768>>>(g_q, W1, b1);
    kC<<<dim3(PP / KC_ROWS, BB / KC_BI), 256, KC_SMEM_BYTES>>>(b2, W3, b3, out);
}

// round 17
// speedup vs baseline: 1.2637x; 1.0994x over previous
#include <cuda_runtime.h>
#include <cuda_bf16.h>
#include <math.h>
#include <stdint.h>

#define BB 16
#define PP 16384
#define MM 2048
#define D_Z 512
#define D_PHI 256
#define D_R 64
#define H1 96
#define H2 96

// scratch (no allocation allowed)
__device__ float g_A[BB * H1];
__device__ float g_Cp[PP * H1];
// precomputed bf16 hi/lo weights, [n][k2] layout (k2 = packed k-pair index)
__device__ uint32_t g_W1hi[96 * 416];
__device__ uint32_t g_W1lo[96 * 416];
__device__ uint32_t g_W2hi[96 * 48];
__device__ uint32_t g_W2lo[96 * 48];

// sigmoid-form tanh-GELU: x * sigma(1.5957691x + 0.0713548x^3)
// max abs dev from exact erf-gelu ~3.5e-4; 8 ops, 2 MUFU, branch-free
__device__ __forceinline__ float fast_gelu(float x) {
    float x2 = x * x;
    float v  = x * fmaf(0.07135481627f, x2, 1.5957691216f);
    float e  = __expf(-v);
    return __fdividef(x, 1.0f + e);
}

// ---- bf16 split helpers ----
__device__ __forceinline__ void bf16split(float x, unsigned short& h, unsigned short& l) {
    __nv_bfloat16 bh = __float2bfloat16_rn(x);
    float fh = __bfloat162float(bh);
    __nv_bfloat16 bl = __float2bfloat16_rn(x - fh);
    h = __bfloat16_as_ushort(bh);
    l = __bfloat16_as_ushort(bl);
}
__device__ __forceinline__ uint32_t packu(unsigned short lo16, unsigned short hi16) {
    return (uint32_t)lo16 | ((uint32_t)hi16 << 16);
}

// bf16 mma.sync (sm_80+ baseline, legal on compute_100)
__device__ __forceinline__ void mma_bf16(float* c,
                                         uint32_t a0, uint32_t a1, uint32_t a2, uint32_t a3,
                                         uint32_t b0, uint32_t b1) {
    asm volatile(
        "mma.sync.aligned.m16n8k16.row.col.f32.bf16.bf16.f32 "
        "{%0,%1,%2,%3}, {%4,%5,%6,%7}, {%8,%9}, {%0,%1,%2,%3};"
        : "+f"(c[0]), "+f"(c[1]), "+f"(c[2]), "+f"(c[3])
        : "r"(a0), "r"(a1), "r"(a2), "r"(a3), "r"(b0), "r"(b1));
}

// ---------------------------------------------------------------------------
// Kernel P: precompute bf16 hi/lo splits of W1[512:,:] and W2, [n][k2] layout.
// ---------------------------------------------------------------------------
__global__ void kP(const float* __restrict__ W1, const float* __restrict__ W2) {
    int idx = blockIdx.x * blockDim.x + threadIdx.x;
    if (idx < 96 * 416) {
        int n = idx / 416, k2 = idx - n * 416;
        float w0 = W1[(size_t)(D_Z + 2 * k2) * H1 + n];
        float w1 = W1[(size_t)(D_Z + 2 * k2 + 1) * H1 + n];
        unsigned short h0, l0, h1v, l1v;
        bf16split(w0, h0, l0);
        bf16split(w1, h1v, l1v);
        g_W1hi[idx] = packu(h0, h1v);
        g_W1lo[idx] = packu(l0, l1v);
    } else if (idx < 96 * 416 + 96 * 48) {
        int t = idx - 96 * 416;
        int n = t / 48, k2 = t - n * 48;
        float w0 = W2[(size_t)(2 * k2) * H2 + n];
        float w1 = W2[(size_t)(2 * k2 + 1) * H2 + n];
        unsigned short h0, l0, h1v, l1v;
        bf16split(w0, h0, l0);
        bf16split(w1, h1v, l1v);
        g_W2hi[t] = packu(h0, h1v);
        g_W2lo[t] = packu(l0, l1v);
    }
}

// ---------------------------------------------------------------------------
// Kernel A: A[b,j] = b1[j] + sum_k g_q[b,k] * W1[k,j]
// ---------------------------------------------------------------------------
__global__ void __launch_bounds__(768) kA(const float* __restrict__ g_q,
                                          const float* __restrict__ W1,
                                          const float* __restrict__ b1) {
    __shared__ float gq_sh[D_Z];
    __shared__ float psum[7 * 96];
    int b = blockIdx.x;
    int tid = threadIdx.x;
    for (int t = tid; t < D_Z; t += 768) gq_sh[t] = g_q[b * D_Z + t];
    __syncthreads();
    int ks = tid / 96, j = tid % 96;
    float s = 0.f;
    const float* w = W1 + (size_t)(ks * 64) * H1 + j;
    #pragma unroll 8
    for (int k = 0; k < 64; k++)
        s += gq_sh[ks * 64 + k] * w[(size_t)k * H1];
    if (ks > 0) psum[(ks - 1) * 96 + j] = s;
    __syncthreads();
    if (ks == 0) {
        #pragma unroll
        for (int i = 0; i < 7; i++) s += psum[i * 96 + j];
        g_A[b * H1 + j] = s + b1[j];
    }
}

// ---------------------------------------------------------------------------
// Kernel B (mma.sync bf16 hi/lo, fused 3-in-1 pass loop): Cp = feat @ W1[512:]
// (unchanged from round 16)
// ---------------------------------------------------------------------------
#define KB_STR 36
#define KB_ROWS 64

__global__ void __launch_bounds__(256, 3) kB(const float* __restrict__ Phi,
                                             const void* __restrict__ pair_index,
                                             const float* __restrict__ rel) {
    __shared__ uint32_t Ahi[KB_ROWS * KB_STR];
    __shared__ uint32_t Alo[KB_ROWS * KB_STR];
    __shared__ uint32_t Whi[96 * KB_STR];
    __shared__ uint32_t Wlo[96 * KB_STR];
    __shared__ int pi_sh[KB_ROWS * 2];

    int tid  = threadIdx.x;
    int wid  = tid >> 5;
    int lane = tid & 31;
    int gid  = lane >> 2;
    int tig  = lane & 3;
    int p0   = blockIdx.x * KB_ROWS;

    {
        const int* p32 = (const int*)pair_index;
        int w = 0;
        if (tid < KB_ROWS * 2) w = p32[(size_t)p0 * 2 + tid];
        int any_odd = __syncthreads_or((tid & 1) ? w : 0);
        if (tid < KB_ROWS * 2) {
            int v;
            if (any_odd != 0) v = w;
            else {
                const long long* p64 = (const long long*)pair_index;
                v = (int)p64[(size_t)p0 * 2 + tid];
            }
            v = v < 0 ? 0 : (v >= MM ? MM - 1 : v);
            pi_sh[tid] = v;
        }
    }

    int mrow = (wid >> 1) * 16;
    int ncol = (wid & 1) * 48;

    float c[6][4];
    #pragma unroll
    for (int nt = 0; nt < 6; nt++)
        #pragma unroll
        for (int r = 0; r < 4; r++) c[nt][r] = 0.f;

    for (int ch = 0; ch < 13; ch++) {
        int mode  = ch >> 2;
        int cbase = (ch & 3) * 64;
        __syncthreads();

        #pragma unroll 2
        for (int idx = tid; idx < KB_ROWS * 32; idx += 256) {
            int pp  = idx >> 5;
            int kk2 = idx & 31;
            float f0, f1;
            if (mode == 3) {
                const float* rp = rel + (size_t)(p0 + pp) * D_R + kk2 * 2;
                f0 = rp[0]; f1 = rp[1];
            } else {
                int i0 = pi_sh[pp * 2];
                int j0 = pi_sh[pp * 2 + 1];
                const float* pi_ = Phi + (size_t)i0 * D_PHI + cbase + kk2 * 2;
                const float* pj_ = Phi + (size_t)j0 * D_PHI + cbase + kk2 * 2;
                float a0v = pi_[0], a1v = pi_[1];
                float c0v = pj_[0], c1v = pj_[1];
                if (mode == 0)      { f0 = a0v + c0v;        f1 = a1v + c1v; }
                else if (mode == 1) { f0 = fabsf(a0v - c0v); f1 = fabsf(a1v - c1v); }
                else                { f0 = a0v * c0v;        f1 = a1v * c1v; }
            }
            unsigned short h0, l0, h1v, l1v;
            bf16split(f0, h0, l0);
            bf16split(f1, h1v, l1v);
            Ahi[pp * KB_STR + kk2] = packu(h0, h1v);
            Alo[pp * KB_STR + kk2] = packu(l0, l1v);
        }

        #pragma unroll 4
        for (int idx = tid; idx < 96 * 32; idx += 256) {
            int n   = idx >> 5;
            int kk2 = idx & 31;
            Whi[n * KB_STR + kk2] = g_W1hi[n * 416 + ch * 32 + kk2];
            Wlo[n * KB_STR + kk2] = g_W1lo[n * 416 + ch * 32 + kk2];
        }
        __syncthreads();

        #pragma unroll
        for (int ks = 0; ks < 4; ks++) {
            int kw = ks * 8;
            int r = mrow + gid;
            uint32_t ah0 = Ahi[(r)     * KB_STR + kw + tig];
            uint32_t ah1 = Ahi[(r + 8) * KB_STR + kw + tig];
            uint32_t ah2 = Ahi[(r)     * KB_STR + kw + 4 + tig];
            uint32_t ah3 = Ahi[(r + 8) * KB_STR + kw + 4 + tig];
            uint32_t al0 = Alo[(r)     * KB_STR + kw + tig];
            uint32_t al1 = Alo[(r + 8) * KB_STR + kw + tig];
            uint32_t al2 = Alo[(r)     * KB_STR + kw + 4 + tig];
            uint32_t al3 = Alo[(r + 8) * KB_STR + kw + 4 + tig];
            #pragma unroll
            for (int nt = 0; nt < 6; nt++) {
                int n = ncol + nt * 8 + gid;
                uint32_t bh0 = Whi[n * KB_STR + kw + tig];
                uint32_t bh1 = Whi[n * KB_STR + kw + 4 + tig];
                uint32_t bl0 = Wlo[n * KB_STR + kw + tig];
                uint32_t bl1 = Wlo[n * KB_STR + kw + 4 + tig];
                mma_bf16(c[nt], ah0, ah1, ah2, ah3, bh0, bh1);
                mma_bf16(c[nt], al0, al1, al2, al3, bh0, bh1);
                mma_bf16(c[nt], ah0, ah1, ah2, ah3, bl0, bl1);
            }
        }
    }

    #pragma unroll
    for (int rh = 0; rh < 2; rh++) {
        int row = mrow + rh * 8 + gid;
        float* o = g_Cp + (size_t)(p0 + row) * H1;
        #pragma unroll
        for (int nt = 0; nt < 6; nt++) {
            int col = ncol + nt * 8 + tig * 2;
            *(float2*)(o + col) = make_float2(c[nt][rh * 2], c[nt][rh * 2 + 1]);
        }
    }
}

// ---------------------------------------------------------------------------
// Kernel C (persistent CTAs, mma.sync bf16 hi/lo fused):
// out[b,p] = gelu(gelu(A[b]+Cp[p])@W2+b2)@W3+b3
// Grid = 444 (148 SMs x 3 resident). Each CTA stages W2 + all 16 A rows ONCE,
// then loops over a contiguous range of the 4096 work items
// (p-tile-major, b-inner => Cp stays in registers across 16 consecutive items).
// ---------------------------------------------------------------------------
#define SA_STR 52
#define KC_ROWS 64
#define KC_GRID 444
#define KC_NT   (PP / KC_ROWS * BB)      // 4096 work items
#define AHI_OFF 0
#define ALO_OFF 3328
#define BHI_OFF 6656
#define BLO_OFF 11648
#define AALL_OFF 16640                   // 16 x 96 = 1536
#define B2_OFF  18176
#define W3_OFF  18272
#define PS_OFF  18368
#define KC_SMEM_BYTES ((18368 + 128) * 4)

__global__ void __launch_bounds__(256, 3) kC(const float* __restrict__ b2,
                                             const float* __restrict__ W3,
                                             const float* __restrict__ b3,
                                             float* __restrict__ out) {
    extern __shared__ uint32_t smw[];
    uint32_t* Ahi = smw + AHI_OFF;      // 64 x 52
    uint32_t* Alo = smw + ALO_OFF;      // 64 x 52
    uint32_t* Bhi = smw + BHI_OFF;      // 96 x 52
    uint32_t* Blo = smw + BLO_OFF;      // 96 x 52
    float* Aall = (float*)(smw + AALL_OFF);  // 16 x 96
    float* b2f  = (float*)(smw + B2_OFF);
    float* W3f  = (float*)(smw + W3_OFF);
    float* ps   = (float*)(smw + PS_OFF);    // 2 x 64

    int tid  = threadIdx.x;
    int wid  = tid >> 5;
    int lane = tid & 31;
    int gid  = lane >> 2;
    int tig  = lane & 3;

    if (tid < 96) { b2f[tid] = b2[tid]; W3f[tid] = W3[tid]; }
    for (int idx = tid; idx < BB * 96; idx += 256)
        Aall[idx] = g_A[idx];
    for (int idx = tid; idx < 96 * 48; idx += 256) {
        int n = idx / 48, k2 = idx - n * 48;
        Bhi[n * SA_STR + k2] = g_W2hi[idx];
        Blo[n * SA_STR + k2] = g_W2lo[idx];
    }
    float b3v = b3[0];
    __syncthreads();

    int row = tid >> 2, q4 = tid & 3;
    int mrow = (wid >> 1) * 16;
    int ncol = (wid & 1) * 48;

    int t0 = (int)(((long long)blockIdx.x * KC_NT) / KC_GRID);
    int t1 = (int)(((long long)(blockIdx.x + 1) * KC_NT) / KC_GRID);

    int cur_p = -1;
    float cp[24];

    for (int t = t0; t < t1; t++) {
        int p0g = t >> 4;           // p-tile index (b-inner order)
        int b   = t & 15;

        if (p0g != cur_p) {
            cur_p = p0g;
            const float4* cp4 =
                (const float4*)(g_Cp + ((size_t)p0g * KC_ROWS + row) * H1) + q4 * 6;
            #pragma unroll
            for (int q = 0; q < 6; q++) {
                float4 v = cp4[q];
                cp[q * 4 + 0] = v.x; cp[q * 4 + 1] = v.y;
                cp[q * 4 + 2] = v.z; cp[q * 4 + 3] = v.w;
            }
        }

        // ---- build h1 = fast_gelu(A[b] + cp), split hi/lo into smem ----
        {
            const float* Af = Aall + b * 96 + q4 * 24;
            uint32_t* ah = Ahi + row * SA_STR + q4 * 12;
            uint32_t* al = Alo + row * SA_STR + q4 * 12;
            #pragma unroll
            for (int q = 0; q < 6; q++) {
                int k = q * 4;
                float g0 = fast_gelu(Af[k + 0] + cp[k + 0]);
                float g1 = fast_gelu(Af[k + 1] + cp[k + 1]);
                float g2 = fast_gelu(Af[k + 2] + cp[k + 2]);
                float g3 = fast_gelu(Af[k + 3] + cp[k + 3]);
                unsigned short h0, l0, h1v, l1v, h2, l2, h3, l3;
                bf16split(g0, h0, l0); bf16split(g1, h1v, l1v);
                bf16split(g2, h2, l2); bf16split(g3, h3, l3);
                ah[q * 2 + 0] = packu(h0, h1v);
                ah[q * 2 + 1] = packu(h2, h3);
                al[q * 2 + 0] = packu(l0, l1v);
                al[q * 2 + 1] = packu(l2, l3);
            }
        }
        __syncthreads();

        // ---- MMA: fused hi/lo, 6 k16-steps, warp tile 16x48 ----
        float c[6][4];
        #pragma unroll
        for (int nt = 0; nt < 6; nt++)
            #pragma unroll
            for (int r = 0; r < 4; r++) c[nt][r] = 0.f;

        #pragma unroll
        for (int ks = 0; ks < 6; ks++) {
            int kw = ks * 8;
            int r = mrow + gid;
            uint32_t ah0 = Ahi[(r)     * SA_STR + kw + tig];
            uint32_t ah1 = Ahi[(r + 8) * SA_STR + kw + tig];
            uint32_t ah2 = Ahi[(r)     * SA_STR + kw + 4 + tig];
            uint32_t ah3 = Ahi[(r + 8) * SA_STR + kw + 4 + tig];
            uint32_t al0 = Alo[(r)     * SA_STR + kw + tig];
            uint32_t al1 = Alo[(r + 8) * SA_STR + kw + tig];
            uint32_t al2 = Alo[(r)     * SA_STR + kw + 4 + tig];
            uint32_t al3 = Alo[(r + 8) * SA_STR + kw + 4 + tig];
            #pragma unroll
            for (int nt = 0; nt < 6; nt++) {
                int n = ncol + nt * 8 + gid;
                uint32_t bh0 = Bhi[n * SA_STR + kw + tig];
                uint32_t bh1 = Bhi[n * SA_STR + kw + 4 + tig];
                uint32_t bl0 = Blo[n * SA_STR + kw + tig];
                uint32_t bl1 = Blo[n * SA_STR + kw + 4 + tig];
                mma_bf16(c[nt], ah0, ah1, ah2, ah3, bh0, bh1);
                mma_bf16(c[nt], al0, al1, al2, al3, bh0, bh1);
                mma_bf16(c[nt], ah0, ah1, ah2, ah3, bl0, bl1);
            }
        }

        // ---- epilogue: bias + gelu + W3-dot, shfl reduce, combine halves ----
        #pragma unroll
        for (int rh = 0; rh < 2; rh++) {
            float part = 0.f;
            #pragma unroll
            for (int nt = 0; nt < 6; nt++) {
                int col = ncol + nt * 8 + tig * 2;
                float v0 = c[nt][rh * 2 + 0] + b2f[col];
                float v1 = c[nt][rh * 2 + 1] + b2f[col + 1];
                part += fast_gelu(v0) * W3f[col];
                part += fast_gelu(v1) * W3f[col + 1];
            }
            part += __shfl_xor_sync(0xFFFFFFFF, part, 1);
            part += __shfl_xor_sync(0xFFFFFFFF, part, 2);
            if (tig == 0) {
                int rr = mrow + rh * 8 + gid;
                ps[(wid & 1) * KC_ROWS + rr] = part;
            }
        }
        __syncthreads();

        if (tid < KC_ROWS)
            out[(size_t)b * PP + p0g * KC_ROWS + tid] =
                ps[tid] + ps[KC_ROWS + tid] + b3v;
        __syncthreads();
    }
}

// ---------------------------------------------------------------------------
extern "C" void kernel_launch(void* const* d_in, const int* in_sizes, int n_in,
                              void* d_out, int out_size) {
    const float* g_q = (const float*)d_in[0];
    const float* Phi = (const float*)d_in[1];
    const void*  pin = (const void*)d_in[2];
    const float* rel = (const float*)d_in[3];
    const float* W1  = (const float*)d_in[4];
    const float* b1  = (const float*)d_in[5];
    const float* W2  = (const float*)d_in[6];
    const float* b2  = (const float*)d_in[7];
    const float* W3  = (const float*)d_in[8];
    const float* b3  = (const float*)d_in[9];
    float* out = (float*)d_out;

    cudaFuncSetAttribute(kC, cudaFuncAttributeMaxDynamicSharedMemorySize,
                         KC_SMEM_BYTES);

    kP<<<(96 * 416 + 96 * 48 + 255) / 256, 256>>>(W1, W2);
    kB<<<PP / KB_ROWS, 256>>>(Phi, pin, rel);
    kA<<<BB, 768>>>(g_q, W1, b1);
    kC<<<KC_GRID, 256, KC_SMEM_BYTES>>>(b2, W3, b3, out);
}